// round 2
// baseline (speedup 1.0000x reference)
#include <cuda_runtime.h>
#include <math.h>

#define NB   8
#define CIN  256
#define HH   64
#define WW   64
#define COUT 256
#define KK9  9
#define HW   4096   // 64*64
#define CK   (CIN*KK9)  // 2304

// Scratch (static device globals; no runtime allocation)
__device__ float g_offset[NB * 18 * HW];     // [N][18][Ho*Wo]
__device__ float g_w2t[CK * COUT];           // [ck][o]  (transposed w2)

// ---------------------------------------------------------------------------
// Kernel T: transpose w2 [Cout][C*9] -> w2t [C*9][Cout] (coalesced writes)
// ---------------------------------------------------------------------------
__global__ void k_transpose(const float* __restrict__ w2) {
    int ck = blockIdx.x;        // 0..2303
    int o  = threadIdx.x;       // 0..255
    g_w2t[ck * COUT + o] = w2[o * CK + ck];
}

// ---------------------------------------------------------------------------
// Kernel 1: offset-predicting 3x3 conv (18 output channels), pad=1 stride=1
// Block: one n, two full output rows (2x64 = 128 positions). 256 threads.
// ---------------------------------------------------------------------------
__global__ __launch_bounds__(256) void k_off(const float* __restrict__ x,
                                             const float* __restrict__ w1) {
    __shared__ float xs[8][4][66];   // c-chunk, 4 input rows, 66 cols (halo)
    __shared__ float ws[8][9][18];   // [c][tap][o]

    int n  = blockIdx.x >> 5;            // 8 images
    int y0 = (blockIdx.x & 31) * 2;      // output row base
    int tid = threadIdx.x;
    int p    = tid >> 1;                 // 0..127 position in tile
    int half = tid & 1;                  // which 9 output channels
    int r   = p >> 6;                    // row within tile (0/1)
    int col = p & 63;
    int o0  = half * 9;

    float acc[9];
#pragma unroll
    for (int j = 0; j < 9; j++) acc[j] = 0.f;

    for (int cb = 0; cb < CIN; cb += 8) {
        // load input patch (zero-padded)
        for (int l = tid; l < 8 * 4 * 66; l += 256) {
            int c  = l / 264;
            int rem = l - c * 264;
            int y  = rem / 66;
            int xc = rem - y * 66;
            int gy = y0 - 1 + y;
            int gx = xc - 1;
            float v = 0.f;
            if ((unsigned)gy < 64u && (unsigned)gx < 64u)
                v = x[((n * CIN + cb + c) * 64 + gy) * 64 + gx];
            xs[c][y][xc] = v;
        }
        // load weights chunk
        for (int l = tid; l < 8 * 9 * 18; l += 256) {
            int o = l % 18;
            int k = (l / 18) % 9;
            int c = l / 162;
            ws[c][k][o] = w1[(o * CIN + cb + c) * 9 + k];
        }
        __syncthreads();

#pragma unroll
        for (int c = 0; c < 8; c++) {
            float xv[9];
#pragma unroll
            for (int ky = 0; ky < 3; ky++)
#pragma unroll
                for (int kx = 0; kx < 3; kx++)
                    xv[ky * 3 + kx] = xs[c][r + ky][col + kx];
#pragma unroll
            for (int k = 0; k < 9; k++) {
                float v = xv[k];
#pragma unroll
                for (int j = 0; j < 9; j++)
                    acc[j] += ws[c][k][o0 + j] * v;
            }
        }
        __syncthreads();
    }

    int hw = (y0 + r) * 64 + col;
#pragma unroll
    for (int j = 0; j < 9; j++)
        g_offset[(n * 18 + o0 + j) * HW + hw] = acc[j];
}

// ---------------------------------------------------------------------------
// Kernel 2: deformable conv main contraction.
// Block: one n, 32 consecutive spatial positions, all 256 output channels.
// 256 threads: otid = tid&31 (o-groups), ptid = tid>>5 (4 positions each).
// Thread micro-tile: 8 o x 4 p register accumulators.
// ---------------------------------------------------------------------------
__global__ __launch_bounds__(256) void k_main(const float* __restrict__ x,
                                              const float* __restrict__ b2,
                                              float* __restrict__ out) {
    __shared__ int   tab_y0[288];
    __shared__ int   tab_x0[288];
    __shared__ float tab_wy[288];
    __shared__ float tab_wx[288];
    __shared__ float w2_sm[36 * 256];   // [ck_local][o]
    __shared__ float val_sm[36 * 32];   // [ck_local][p]

    int n     = blockIdx.x >> 7;          // 8 images x 128 tiles
    int pbase = (blockIdx.x & 127) * 32;  // flattened hw base
    int tid   = threadIdx.x;
    int otid  = tid & 31;
    int ptid  = tid >> 5;

    // Bilinear sampling table: 9 taps x 32 positions (288 entries, 256 threads
    // -> MUST grid-stride; round-1 bug was a bare `if (tid < 288)` guard)
    for (int t = tid; t < 288; t += 256) {
        int tap = t >> 5;
        int p   = t & 31;
        int hw  = pbase + p;
        int h   = hw >> 6;
        int w   = hw & 63;
        float dy = g_offset[(n * 18 + 2 * tap)     * HW + hw];
        float dx = g_offset[(n * 18 + 2 * tap + 1) * HW + hw];
        float py = (float)(h - 1 + tap / 3) + dy;
        float px = (float)(w - 1 + tap % 3) + dx;
        float fy = floorf(py), fx = floorf(px);
        tab_y0[t] = (int)fy;
        tab_x0[t] = (int)fx;
        tab_wy[t] = py - fy;
        tab_wx[t] = px - fx;
    }

    float4 acc[8];
#pragma unroll
    for (int j = 0; j < 8; j++) acc[j] = make_float4(0.f, 0.f, 0.f, 0.f);

    __syncthreads();

    for (int cb = 0; cb < CIN; cb += 4) {
        // stage w2t chunk: 36 rows x 256 o = 2304 float4 loads (contiguous)
        const float4* w2src = (const float4*)(g_w2t + cb * 9 * COUT);
        float4* w2dst = (float4*)w2_sm;
#pragma unroll
        for (int l = 0; l < 9; l++)
            w2dst[tid + l * 256] = w2src[tid + l * 256];

        // gather val: 36 ck x 32 p
        for (int e = tid; e < 1152; e += 256) {
            int ck = e >> 5;
            int p  = e & 31;
            int cl  = ck / 9;
            int tap = ck - cl * 9;
            int t = tap * 32 + p;
            int y0 = tab_y0[t], x0 = tab_x0[t];
            float wy = tab_wy[t], wx = tab_wx[t];
            const float* xp = x + ((n * CIN + cb + cl) << 12);
            float v00 = 0.f, v01 = 0.f, v10 = 0.f, v11 = 0.f;
            bool yi0 = (unsigned)y0       < 64u;
            bool yi1 = (unsigned)(y0 + 1) < 64u;
            bool xi0 = (unsigned)x0       < 64u;
            bool xi1 = (unsigned)(x0 + 1) < 64u;
            int r0 = y0 << 6;
            int r1 = r0 + 64;
            if (yi0 && xi0) v00 = __ldg(xp + r0 + x0);
            if (yi0 && xi1) v01 = __ldg(xp + r0 + x0 + 1);
            if (yi1 && xi0) v10 = __ldg(xp + r1 + x0);
            if (yi1 && xi1) v11 = __ldg(xp + r1 + x0 + 1);
            float vt = v00 + wx * (v01 - v00);
            float vb = v10 + wx * (v11 - v10);
            val_sm[e] = vt + wy * (vb - vt);
        }
        __syncthreads();

        // contraction: acc[8o][4p] += w2[o,ck] * val[ck,p]
#pragma unroll 6
        for (int ck = 0; ck < 36; ck++) {
            float4 v  = *(const float4*)(val_sm + ck * 32 + ptid * 4);
            float4 wa = *(const float4*)(w2_sm + ck * 256 + otid * 4);
            float4 wb = *(const float4*)(w2_sm + ck * 256 + 128 + otid * 4);
            float wv[8] = {wa.x, wa.y, wa.z, wa.w, wb.x, wb.y, wb.z, wb.w};
#pragma unroll
            for (int j = 0; j < 8; j++) {
                acc[j].x += wv[j] * v.x;
                acc[j].y += wv[j] * v.y;
                acc[j].z += wv[j] * v.z;
                acc[j].w += wv[j] * v.w;
            }
        }
        __syncthreads();
    }

    // epilogue: bias + store (thread owns o = otid*4+j and 128+otid*4+j)
#pragma unroll
    for (int j = 0; j < 8; j++) {
        int o = (j < 4) ? (otid * 4 + j) : (128 + otid * 4 + (j - 4));
        float bb = b2[o];
        float4 rv = acc[j];
        rv.x += bb; rv.y += bb; rv.z += bb; rv.w += bb;
        *(float4*)(out + ((size_t)(n * COUT + o) * HW) + pbase + ptid * 4) = rv;
    }
}

// ---------------------------------------------------------------------------
extern "C" void kernel_launch(void* const* d_in, const int* in_sizes, int n_in,
                              void* d_out, int out_size) {
    const float* x  = (const float*)d_in[0];
    const float* w1 = (const float*)d_in[1];
    const float* w2 = (const float*)d_in[2];
    const float* b2 = (const float*)d_in[3];
    float* out = (float*)d_out;

    k_transpose<<<CK, COUT>>>(w2);
    k_off<<<NB * 32, 256>>>(x, w1);
    k_main<<<NB * 128, 256>>>(x, b2, out);
}

// round 3
// speedup vs baseline: 1.0265x; 1.0265x over previous
#include <cuda_runtime.h>
#include <math.h>

#define NB   8
#define CIN  256
#define HH   64
#define WW   64
#define COUT 256
#define KK9  9
#define HW   4096   // 64*64
#define CK   (CIN*KK9)  // 2304

// Scratch (static device globals; no runtime allocation)
__device__ float g_offset[NB * 18 * HW];     // [N][18][Ho*Wo]
__device__ float g_w2t[CK * COUT];           // [ck][o]  (transposed w2)

// ---------------------------------------------------------------------------
// Kernel T: transpose w2 [Cout][C*9] -> w2t [C*9][Cout] (coalesced writes)
// ---------------------------------------------------------------------------
__global__ void k_transpose(const float* __restrict__ w2) {
    int ck = blockIdx.x;        // 0..2303
    int o  = threadIdx.x;       // 0..255
    g_w2t[ck * COUT + o] = w2[o * CK + ck];
}

// ---------------------------------------------------------------------------
// Kernel 1: offset-predicting 3x3 conv (18 output channels), pad=1 stride=1
// Block: one n, two full output rows (2x64 = 128 positions). 256 threads.
// ---------------------------------------------------------------------------
__global__ __launch_bounds__(256) void k_off(const float* __restrict__ x,
                                             const float* __restrict__ w1) {
    __shared__ float xs[8][4][66];   // c-chunk, 4 input rows, 66 cols (halo)
    __shared__ float ws[8][9][18];   // [c][tap][o]

    int n  = blockIdx.x >> 5;            // 8 images
    int y0 = (blockIdx.x & 31) * 2;      // output row base
    int tid = threadIdx.x;
    int p    = tid >> 1;                 // 0..127 position in tile
    int half = tid & 1;                  // which 9 output channels
    int r   = p >> 6;                    // row within tile (0/1)
    int col = p & 63;
    int o0  = half * 9;

    float acc[9];
#pragma unroll
    for (int j = 0; j < 9; j++) acc[j] = 0.f;

    for (int cb = 0; cb < CIN; cb += 8) {
        // load input patch (zero-padded)
        for (int l = tid; l < 8 * 4 * 66; l += 256) {
            int c  = l / 264;
            int rem = l - c * 264;
            int y  = rem / 66;
            int xc = rem - y * 66;
            int gy = y0 - 1 + y;
            int gx = xc - 1;
            float v = 0.f;
            if ((unsigned)gy < 64u && (unsigned)gx < 64u)
                v = x[((n * CIN + cb + c) * 64 + gy) * 64 + gx];
            xs[c][y][xc] = v;
        }
        // load weights chunk
        for (int l = tid; l < 8 * 9 * 18; l += 256) {
            int o = l % 18;
            int k = (l / 18) % 9;
            int c = l / 162;
            ws[c][k][o] = w1[(o * CIN + cb + c) * 9 + k];
        }
        __syncthreads();

#pragma unroll
        for (int c = 0; c < 8; c++) {
            float xv[9];
#pragma unroll
            for (int ky = 0; ky < 3; ky++)
#pragma unroll
                for (int kx = 0; kx < 3; kx++)
                    xv[ky * 3 + kx] = xs[c][r + ky][col + kx];
#pragma unroll
            for (int k = 0; k < 9; k++) {
                float v = xv[k];
#pragma unroll
                for (int j = 0; j < 9; j++)
                    acc[j] += ws[c][k][o0 + j] * v;
            }
        }
        __syncthreads();
    }

    int hw = (y0 + r) * 64 + col;
#pragma unroll
    for (int j = 0; j < 9; j++)
        g_offset[(n * 18 + o0 + j) * HW + hw] = acc[j];
}

// ---------------------------------------------------------------------------
// Kernel 2: deformable conv main contraction.
// Block: one n, 32 consecutive spatial positions, all 256 output channels.
// 256 threads: otid = tid&31 (o-groups), ptid = tid>>5 (4 positions each).
// Thread micro-tile: 8 o x 4 p, held as 16 packed f32x2 accumulators
// (pairs along o). Inner product uses Blackwell fma.rn.f32x2 (FFMA2) —
// exact fp32 semantics, 2x fma-pipe throughput.
// ---------------------------------------------------------------------------
__global__ __launch_bounds__(256) void k_main(const float* __restrict__ x,
                                              const float* __restrict__ b2,
                                              float* __restrict__ out) {
    __shared__ int   tab_y0[288];
    __shared__ int   tab_x0[288];
    __shared__ float tab_wy[288];
    __shared__ float tab_wx[288];
    __shared__ float w2_sm[36 * 256];   // [ck_local][o]
    __shared__ float val_sm[36 * 32];   // [ck_local][p]

    int n     = blockIdx.x >> 7;          // 8 images x 128 tiles
    int pbase = (blockIdx.x & 127) * 32;  // flattened hw base
    int tid   = threadIdx.x;
    int otid  = tid & 31;
    int ptid  = tid >> 5;

    // Bilinear sampling table: 9 taps x 32 positions (288 entries -> stride)
    for (int t = tid; t < 288; t += 256) {
        int tap = t >> 5;
        int p   = t & 31;
        int hw  = pbase + p;
        int h   = hw >> 6;
        int w   = hw & 63;
        float dy = g_offset[(n * 18 + 2 * tap)     * HW + hw];
        float dx = g_offset[(n * 18 + 2 * tap + 1) * HW + hw];
        float py = (float)(h - 1 + tap / 3) + dy;
        float px = (float)(w - 1 + tap % 3) + dx;
        float fy = floorf(py), fx = floorf(px);
        tab_y0[t] = (int)fy;
        tab_x0[t] = (int)fx;
        tab_wy[t] = py - fy;
        tab_wx[t] = px - fx;
    }

    unsigned long long acc2[16];   // [q(o-pair)][i(p)] packed f32x2
#pragma unroll
    for (int j = 0; j < 16; j++) acc2[j] = 0ull;

    __syncthreads();

    for (int cb = 0; cb < CIN; cb += 4) {
        // stage w2t chunk: 36 rows x 256 o = 2304 float4 loads (contiguous)
        const float4* w2src = (const float4*)(g_w2t + cb * 9 * COUT);
        float4* w2dst = (float4*)w2_sm;
#pragma unroll
        for (int l = 0; l < 9; l++)
            w2dst[tid + l * 256] = w2src[tid + l * 256];

        // gather val: 36 ck x 32 p
        for (int e = tid; e < 1152; e += 256) {
            int ck = e >> 5;
            int p  = e & 31;
            int cl  = ck / 9;
            int tap = ck - cl * 9;
            int t = tap * 32 + p;
            int y0 = tab_y0[t], x0 = tab_x0[t];
            float wy = tab_wy[t], wx = tab_wx[t];
            const float* xp = x + ((n * CIN + cb + cl) << 12);
            float v00 = 0.f, v01 = 0.f, v10 = 0.f, v11 = 0.f;
            bool yi0 = (unsigned)y0       < 64u;
            bool yi1 = (unsigned)(y0 + 1) < 64u;
            bool xi0 = (unsigned)x0       < 64u;
            bool xi1 = (unsigned)(x0 + 1) < 64u;
            int r0 = y0 << 6;
            int r1 = r0 + 64;
            if (yi0 && xi0) v00 = __ldg(xp + r0 + x0);
            if (yi0 && xi1) v01 = __ldg(xp + r0 + x0 + 1);
            if (yi1 && xi0) v10 = __ldg(xp + r1 + x0);
            if (yi1 && xi1) v11 = __ldg(xp + r1 + x0 + 1);
            float vt = v00 + wx * (v01 - v00);
            float vb = v10 + wx * (v11 - v10);
            val_sm[e] = vt + wy * (vb - vt);
        }
        __syncthreads();

        // contraction: acc2[q][i] (+)= (w[obase],w[obase+1]) * (v[i],v[i])
#pragma unroll 4
        for (int ck = 0; ck < 36; ck++) {
            float4 v  = *(const float4*)(val_sm + ck * 32 + ptid * 4);
            float4 wa = *(const float4*)(w2_sm + ck * 256 + otid * 4);
            float4 wb = *(const float4*)(w2_sm + ck * 256 + 128 + otid * 4);
            unsigned long long wp[4], vp[4];
            asm("mov.b64 %0, {%1, %2};" : "=l"(wp[0]) : "f"(wa.x), "f"(wa.y));
            asm("mov.b64 %0, {%1, %2};" : "=l"(wp[1]) : "f"(wa.z), "f"(wa.w));
            asm("mov.b64 %0, {%1, %2};" : "=l"(wp[2]) : "f"(wb.x), "f"(wb.y));
            asm("mov.b64 %0, {%1, %2};" : "=l"(wp[3]) : "f"(wb.z), "f"(wb.w));
            asm("mov.b64 %0, {%1, %1};" : "=l"(vp[0]) : "f"(v.x));
            asm("mov.b64 %0, {%1, %1};" : "=l"(vp[1]) : "f"(v.y));
            asm("mov.b64 %0, {%1, %1};" : "=l"(vp[2]) : "f"(v.z));
            asm("mov.b64 %0, {%1, %1};" : "=l"(vp[3]) : "f"(v.w));
#pragma unroll
            for (int q = 0; q < 4; q++)
#pragma unroll
                for (int i = 0; i < 4; i++)
                    asm("fma.rn.f32x2 %0, %1, %2, %0;"
                        : "+l"(acc2[q * 4 + i]) : "l"(wp[q]), "l"(vp[i]));
        }
        __syncthreads();
    }

    // epilogue: unpack o-pairs, add bias, float4 stores over p
#pragma unroll
    for (int q = 0; q < 4; q++) {
        float lo[4], hi[4];
#pragma unroll
        for (int i = 0; i < 4; i++)
            asm("mov.b64 {%0, %1}, %2;"
                : "=f"(lo[i]), "=f"(hi[i]) : "l"(acc2[q * 4 + i]));
        int obase = (q < 2) ? (otid * 4 + q * 2) : (128 + otid * 4 + (q - 2) * 2);
        float b0 = b2[obase];
        float b1 = b2[obase + 1];
        float4 r0 = make_float4(lo[0] + b0, lo[1] + b0, lo[2] + b0, lo[3] + b0);
        float4 r1 = make_float4(hi[0] + b1, hi[1] + b1, hi[2] + b1, hi[3] + b1);
        size_t base = (size_t)(n * COUT + obase) * HW + pbase + ptid * 4;
        *(float4*)(out + base)      = r0;
        *(float4*)(out + base + HW) = r1;
    }
}

// ---------------------------------------------------------------------------
extern "C" void kernel_launch(void* const* d_in, const int* in_sizes, int n_in,
                              void* d_out, int out_size) {
    const float* x  = (const float*)d_in[0];
    const float* w1 = (const float*)d_in[1];
    const float* w2 = (const float*)d_in[2];
    const float* b2 = (const float*)d_in[3];
    float* out = (float*)d_out;

    k_transpose<<<CK, COUT>>>(w2);
    k_off<<<NB * 32, 256>>>(x, w1);
    k_main<<<NB * 128, 256>>>(x, b2, out);
}

// round 6
// speedup vs baseline: 1.6762x; 1.6329x over previous
#include <cuda_runtime.h>
#include <cuda_bf16.h>
#include <stdint.h>
#include <math.h>

#define NB   8
#define CIN  256
#define COUT 256
#define HW   4096            // 64*64
#define CK   2304            // CIN*9
#define KC   32              // ck per chunk
#define NCHUNK 72            // 2304/32
#define WSTR 80              // padded SMEM row stride (bytes) for 32 bf16

// ---------------- device scratch ----------------
__device__ float          g_offset[NB * 18 * HW];
// pre-tiled weights: [chunk 72][o 256][ck 32] bf16 hi / lo
__device__ unsigned short g_w2h[NCHUNK * COUT * KC];
__device__ unsigned short g_w2l[NCHUNK * COUT * KC];

// ---------------- SMEM layout (dynamic, bytes) ----------------
#define S_TABA 0                      // int2[1152]   (9 taps x 128 p)
#define S_TABW (S_TABA + 1152*8)      // float4[1152]
#define S_WH   (S_TABW + 1152*16)     // 256 rows x WSTR
#define S_WL   (S_WH + 256*WSTR)
#define S_VH   (S_WL + 256*WSTR)      // 128 rows x WSTR
#define S_VL   (S_VH + 128*WSTR)
#define S_TOTAL (S_VL + 128*WSTR)     // 89088 bytes

// ---------------------------------------------------------------------------
// k_prep: split w2 (fp32 [o][ck]) into bf16 hi/lo, tiled [chunk][o][ck%32]
// ---------------------------------------------------------------------------
__global__ void k_prep(const float* __restrict__ w2) {
    int i = blockIdx.x * 512 + threadIdx.x;     // 1152*512 = 589824 exact
    int o  = i / CK;
    int ck = i - o * CK;
    float v = w2[i];
    unsigned short hb;
    asm("cvt.rn.bf16.f32 %0, %1;" : "=h"(hb) : "f"(v));
    float vh = __uint_as_float(((unsigned)hb) << 16);
    float rem = v - vh;
    unsigned short lb;
    asm("cvt.rn.bf16.f32 %0, %1;" : "=h"(lb) : "f"(rem));
    int dst = ((ck >> 5) * COUT + o) * KC + (ck & 31);
    g_w2h[dst] = hb;
    g_w2l[dst] = lb;
}

// ---------------------------------------------------------------------------
// k_off: offset-predicting 3x3 conv (18 out channels), pad=1 stride=1
// (unchanged from the passing round-2 kernel)
// ---------------------------------------------------------------------------
__global__ __launch_bounds__(256) void k_off(const float* __restrict__ x,
                                             const float* __restrict__ w1) {
    __shared__ float xs[8][4][66];
    __shared__ float ws[8][9][18];

    int n  = blockIdx.x >> 5;
    int y0 = (blockIdx.x & 31) * 2;
    int tid = threadIdx.x;
    int p    = tid >> 1;
    int half = tid & 1;
    int r   = p >> 6;
    int col = p & 63;
    int o0  = half * 9;

    float acc[9];
#pragma unroll
    for (int j = 0; j < 9; j++) acc[j] = 0.f;

    for (int cb = 0; cb < CIN; cb += 8) {
        for (int l = tid; l < 8 * 4 * 66; l += 256) {
            int c  = l / 264;
            int rem = l - c * 264;
            int y  = rem / 66;
            int xc = rem - y * 66;
            int gy = y0 - 1 + y;
            int gx = xc - 1;
            float v = 0.f;
            if ((unsigned)gy < 64u && (unsigned)gx < 64u)
                v = x[((n * CIN + cb + c) * 64 + gy) * 64 + gx];
            xs[c][y][xc] = v;
        }
        for (int l = tid; l < 8 * 9 * 18; l += 256) {
            int o = l % 18;
            int k = (l / 18) % 9;
            int c = l / 162;
            ws[c][k][o] = w1[(o * CIN + cb + c) * 9 + k];
        }
        __syncthreads();

#pragma unroll
        for (int c = 0; c < 8; c++) {
            float xv[9];
#pragma unroll
            for (int ky = 0; ky < 3; ky++)
#pragma unroll
                for (int kx = 0; kx < 3; kx++)
                    xv[ky * 3 + kx] = xs[c][r + ky][col + kx];
#pragma unroll
            for (int k = 0; k < 9; k++) {
                float v = xv[k];
#pragma unroll
                for (int j = 0; j < 9; j++)
                    acc[j] += ws[c][k][o0 + j] * v;
            }
        }
        __syncthreads();
    }

    int hw = (y0 + r) * 64 + col;
#pragma unroll
    for (int j = 0; j < 9; j++)
        g_offset[(n * 18 + o0 + j) * HW + hw] = acc[j];
}

// ---------------------------------------------------------------------------
// HMMA wrapper: D(16x8) += A(16x16,row) * B(16x8,col), bf16 in, f32 accum
// ---------------------------------------------------------------------------
__device__ __forceinline__ void mma16816(float* c, const uint32_t* a,
                                         const uint32_t* b) {
    asm volatile(
        "mma.sync.aligned.m16n8k16.row.col.f32.bf16.bf16.f32 "
        "{%0,%1,%2,%3}, {%4,%5,%6,%7}, {%8,%9}, {%0,%1,%2,%3};"
        : "+f"(c[0]), "+f"(c[1]), "+f"(c[2]), "+f"(c[3])
        : "r"(a[0]), "r"(a[1]), "r"(a[2]), "r"(a[3]), "r"(b[0]), "r"(b[1]));
}

// ---------------------------------------------------------------------------
// k_main: gather -> split-bf16 -> 3-pass mma.sync GEMM, fp32 reg accum
// Block: 512 threads (16 warps, 4m x 4n), tile 256o x 128p, K-chunk 32.
// Grid: 8 n * 32 ptiles = 256 blocks.
// ---------------------------------------------------------------------------
__global__ __launch_bounds__(512, 1) void k_main(const float* __restrict__ x,
                                                 const float* __restrict__ b2,
                                                 float* __restrict__ out) {
    extern __shared__ __align__(16) char smem[];
    int tid = threadIdx.x;
    int wid = tid >> 5;
    int lane = tid & 31;
    int g  = lane >> 2;       // groupID (row within fragment)
    int t2 = lane & 3;        // threadID-in-group (k/col pair select)

    int n     = blockIdx.x >> 5;
    int pbase = (blockIdx.x & 31) * 128;

    int o_base = (wid & 3) * 64;    // warp m-tile base (within 256)
    int p_base = (wid >> 2) * 32;   // warp n-tile base (within 128)

    // ---- bilinear table: 9 taps x 128 positions ----
    for (int t = tid; t < 1152; t += 512) {
        int tap = t >> 7;
        int p   = t & 127;
        int hw  = pbase + p;
        int h   = hw >> 6;
        int w   = hw & 63;
        float dy = g_offset[(n * 18 + 2 * tap)     * HW + hw];
        float dx = g_offset[(n * 18 + 2 * tap + 1) * HW + hw];
        float py = (float)(h - 1 + tap / 3) + dy;
        float px = (float)(w - 1 + tap % 3) + dx;
        float fy = floorf(py), fx = floorf(px);
        float wy = py - fy, wx = px - fx;
        int y0 = (int)fy, x0 = (int)fx;
        float vy0 = ((unsigned)y0       < 64u) ? 1.f : 0.f;
        float vy1 = ((unsigned)(y0 + 1) < 64u) ? 1.f : 0.f;
        float vx0 = ((unsigned)x0       < 64u) ? 1.f : 0.f;
        float vx1 = ((unsigned)(x0 + 1) < 64u) ? 1.f : 0.f;
        float wy0 = (1.f - wy) * vy0, wy1 = wy * vy1;
        float wx0 = (1.f - wx) * vx0, wx1 = wx * vx1;
        int y0c = min(max(y0, 0), 63), y1c = min(max(y0 + 1, 0), 63);
        int x0c = min(max(x0, 0), 63), x1c = min(max(x0 + 1, 0), 63);
        int a00 = (y0c << 6) + x0c;
        int dxo = x1c - x0c;                 // 0 or 1
        int dyo = (y1c - y0c) << 6;          // 0 or 64
        *(int2*)(smem + S_TABA + t * 8)    = make_int2(a00, dxo | (dyo << 16));
        *(float4*)(smem + S_TABW + t * 16) = make_float4(wy0 * wx0, wy0 * wx1,
                                                         wy1 * wx0, wy1 * wx1);
    }

    float acc[4][4][4];
#pragma unroll
    for (int mt = 0; mt < 4; mt++)
#pragma unroll
        for (int nt = 0; nt < 4; nt++)
#pragma unroll
            for (int j = 0; j < 4; j++) acc[mt][nt][j] = 0.f;

    const float* xn = x + ((size_t)n << 20);   // n * CIN * HW

    __syncthreads();

    // ================= K-chunk loop: 72 chunks of 32 ck =================
    for (int cb = 0; cb < NCHUNK; cb++) {
        // ---- stage W chunk (coalesced; pre-tiled layout) ----
        const uint4* wsh = (const uint4*)(g_w2h + cb * COUT * KC);
        const uint4* wsl = (const uint4*)(g_w2l + cb * COUT * KC);
#pragma unroll
        for (int it = 0; it < 2; it++) {
            int l = tid + it * 512;              // 0..1023 uint4 index
            int o   = l >> 2;
            int seg = l & 3;
            *(uint4*)(smem + S_WH + o * WSTR + seg * 16) = wsh[l];
            *(uint4*)(smem + S_WL + o * WSTR + seg * 16) = wsl[l];
        }

        // ---- gather + bf16 split: 128 p x 32 ck ----
        {
            int p = tid & 127;
            int j = tid >> 7;                    // 0..3 (8-ck group)
            int ckg = cb * KC + j * 8;
            int c   = ckg / 9;
            int tap = ckg - c * 9;
            unsigned hbuf[4], lbuf[4];
#pragma unroll
            for (int kk = 0; kk < 8; kk++) {
                int t = (tap << 7) + p;
                int2   ia = *(const int2*)(smem + S_TABA + t * 8);
                float4 wt = *(const float4*)(smem + S_TABW + t * 16);
                const float* xp = xn + ((size_t)c << 12);
                int a00 = ia.x;
                int dxo = ia.y & 0xFFFF;
                int dyo = ia.y >> 16;
                float v = wt.x * __ldg(xp + a00)
                        + wt.y * __ldg(xp + a00 + dxo)
                        + wt.z * __ldg(xp + a00 + dyo)
                        + wt.w * __ldg(xp + a00 + dyo + dxo);
                unsigned short hb;
                asm("cvt.rn.bf16.f32 %0, %1;" : "=h"(hb) : "f"(v));
                float vh = __uint_as_float(((unsigned)hb) << 16);
                float rem = v - vh;
                unsigned short lb;
                asm("cvt.rn.bf16.f32 %0, %1;" : "=h"(lb) : "f"(rem));
                if (kk & 1) { hbuf[kk >> 1] |= ((unsigned)hb) << 16;
                              lbuf[kk >> 1] |= ((unsigned)lb) << 16; }
                else        { hbuf[kk >> 1]  = hb;
                              lbuf[kk >> 1]  = lb; }
                if (++tap == 9) { tap = 0; c++; }
            }
            *(uint4*)(smem + S_VH + p * WSTR + j * 16)
                = make_uint4(hbuf[0], hbuf[1], hbuf[2], hbuf[3]);
            *(uint4*)(smem + S_VL + p * WSTR + j * 16)
                = make_uint4(lbuf[0], lbuf[1], lbuf[2], lbuf[3]);
        }
        __syncthreads();

        // ---- MMA: 2 k-steps x (hh, lh, hl) passes ----
#pragma unroll
        for (int ks = 0; ks < 2; ks++) {
            int kb = ks * 32;                    // byte offset of k0 within row
            uint32_t ah[4][4], al[4][4], bh[4][2], bl[4][2];
#pragma unroll
            for (int mt = 0; mt < 4; mt++) {
                int ro = (o_base + mt * 16 + g) * WSTR + kb + t2 * 4;
                ah[mt][0] = *(const uint32_t*)(smem + S_WH + ro);
                ah[mt][1] = *(const uint32_t*)(smem + S_WH + ro + 8 * WSTR);
                ah[mt][2] = *(const uint32_t*)(smem + S_WH + ro + 16);
                ah[mt][3] = *(const uint32_t*)(smem + S_WH + ro + 8 * WSTR + 16);
                al[mt][0] = *(const uint32_t*)(smem + S_WL + ro);
                al[mt][1] = *(const uint32_t*)(smem + S_WL + ro + 8 * WSTR);
                al[mt][2] = *(const uint32_t*)(smem + S_WL + ro + 16);
                al[mt][3] = *(const uint32_t*)(smem + S_WL + ro + 8 * WSTR + 16);
            }
#pragma unroll
            for (int nt = 0; nt < 4; nt++) {
                int rp = (p_base + nt * 8 + g) * WSTR + kb + t2 * 4;
                bh[nt][0] = *(const uint32_t*)(smem + S_VH + rp);
                bh[nt][1] = *(const uint32_t*)(smem + S_VH + rp + 16);
                bl[nt][0] = *(const uint32_t*)(smem + S_VL + rp);
                bl[nt][1] = *(const uint32_t*)(smem + S_VL + rp + 16);
            }
#pragma unroll
            for (int mt = 0; mt < 4; mt++)
#pragma unroll
                for (int nt = 0; nt < 4; nt++) {
                    mma16816(acc[mt][nt], ah[mt], bh[nt]);
                    mma16816(acc[mt][nt], al[mt], bh[nt]);
                    mma16816(acc[mt][nt], ah[mt], bl[nt]);
                }
        }
        __syncthreads();
    }

    // ---- epilogue: bias + float2 stores ----
#pragma unroll
    for (int mt = 0; mt < 4; mt++) {
        int o0 = o_base + mt * 16 + g;
        float bias0 = b2[o0];
        float bias1 = b2[o0 + 8];
        float* row0 = out + (size_t)(n * COUT + o0) * HW + pbase;
        float* row1 = row0 + 8 * HW;
#pragma unroll
        for (int nt = 0; nt < 4; nt++) {
            int p = p_base + nt * 8 + t2 * 2;
            *(float2*)(row0 + p) = make_float2(acc[mt][nt][0] + bias0,
                                               acc[mt][nt][1] + bias0);
            *(float2*)(row1 + p) = make_float2(acc[mt][nt][2] + bias1,
                                               acc[mt][nt][3] + bias1);
        }
    }
}

// ---------------------------------------------------------------------------
extern "C" void kernel_launch(void* const* d_in, const int* in_sizes, int n_in,
                              void* d_out, int out_size) {
    const float* x  = (const float*)d_in[0];
    const float* w1 = (const float*)d_in[1];
    const float* w2 = (const float*)d_in[2];
    const float* b2 = (const float*)d_in[3];
    float* out = (float*)d_out;

    cudaFuncSetAttribute(k_main, cudaFuncAttributeMaxDynamicSharedMemorySize,
                         S_TOTAL);

    k_prep<<<1152, 512>>>(w2);
    k_off<<<NB * 32, 256>>>(x, w1);
    k_main<<<NB * 32, 512, S_TOTAL>>>(x, b2, out);
}

// round 9
// speedup vs baseline: 1.8984x; 1.1326x over previous
#include <cuda_runtime.h>
#include <cuda_bf16.h>
#include <cuda_fp16.h>
#include <stdint.h>
#include <math.h>

#define NB   8
#define CIN  256
#define COUT 256
#define HW   4096            // 64*64
#define CK   2304            // CIN*9
#define KC   16              // ck per chunk
#define NCH  144             // 2304/16
#define WSTR 48              // SMEM row stride (bytes): 16 fp16 + pad, conflict-free

// ---------------- device scratch ----------------
__device__ float          g_offset[NB * 18 * HW];
// pre-tiled weights: [chunk 144][o 256][ck 16] fp16 hi / lo
__device__ unsigned short g_w2h[NCH * COUT * KC];
__device__ unsigned short g_w2l[NCH * COUT * KC];

// ---------------- SMEM layout (bytes) ----------------
#define S_TABA 0                       // int2[1152]  (9 taps x 128 p)
#define S_TABW 9216                    // float4[1152]
#define S_WH0  27648                   // buf stride 24576 ; WL = WH + 12288
#define S_V0   76800                   // buf stride 6144  (V single fp16)
#define S_TOTAL 89088

// ---------------------------------------------------------------------------
// k_prep: split w2 (fp32 [o][ck]) into fp16 hi/lo, tiled [chunk][o][ck%16]
// ---------------------------------------------------------------------------
__global__ void k_prep(const float* __restrict__ w2) {
    int i = blockIdx.x * 512 + threadIdx.x;     // 1152*512 = 589824 exact
    int o  = i / CK;
    int ck = i - o * CK;
    float v = w2[i];
    unsigned short hb, lb;
    asm("cvt.rn.f16.f32 %0, %1;" : "=h"(hb) : "f"(v));
    float vh;
    asm("cvt.f32.f16 %0, %1;" : "=f"(vh) : "h"(hb));
    float rem = v - vh;
    asm("cvt.rn.f16.f32 %0, %1;" : "=h"(lb) : "f"(rem));
    int dst = ((ck >> 4) * COUT + o) * KC + (ck & 15);
    g_w2h[dst] = hb;
    g_w2l[dst] = lb;
}

// ---------------------------------------------------------------------------
// k_off: offset-predicting 3x3 conv (18 out channels), pad=1 stride=1
// ---------------------------------------------------------------------------
__global__ __launch_bounds__(256) void k_off(const float* __restrict__ x,
                                             const float* __restrict__ w1) {
    __shared__ float xs[8][4][66];
    __shared__ float ws[8][9][18];

    int n  = blockIdx.x >> 5;
    int y0 = (blockIdx.x & 31) * 2;
    int tid = threadIdx.x;
    int p    = tid >> 1;
    int half = tid & 1;
    int r   = p >> 6;
    int col = p & 63;
    int o0  = half * 9;

    float acc[9];
#pragma unroll
    for (int j = 0; j < 9; j++) acc[j] = 0.f;

    for (int cb = 0; cb < CIN; cb += 8) {
        for (int l = tid; l < 8 * 4 * 66; l += 256) {
            int c  = l / 264;
            int rem = l - c * 264;
            int y  = rem / 66;
            int xc = rem - y * 66;
            int gy = y0 - 1 + y;
            int gx = xc - 1;
            float v = 0.f;
            if ((unsigned)gy < 64u && (unsigned)gx < 64u)
                v = x[((n * CIN + cb + c) * 64 + gy) * 64 + gx];
            xs[c][y][xc] = v;
        }
        for (int l = tid; l < 8 * 9 * 18; l += 256) {
            int o = l % 18;
            int k = (l / 18) % 9;
            int c = l / 162;
            ws[c][k][o] = w1[(o * CIN + cb + c) * 9 + k];
        }
        __syncthreads();

#pragma unroll
        for (int c = 0; c < 8; c++) {
            float xv[9];
#pragma unroll
            for (int ky = 0; ky < 3; ky++)
#pragma unroll
                for (int kx = 0; kx < 3; kx++)
                    xv[ky * 3 + kx] = xs[c][r + ky][col + kx];
#pragma unroll
            for (int k = 0; k < 9; k++) {
                float v = xv[k];
#pragma unroll
                for (int j = 0; j < 9; j++)
                    acc[j] += ws[c][k][o0 + j] * v;
            }
        }
        __syncthreads();
    }

    int hw = (y0 + r) * 64 + col;
#pragma unroll
    for (int j = 0; j < 9; j++)
        g_offset[(n * 18 + o0 + j) * HW + hw] = acc[j];
}

// ---------------------------------------------------------------------------
// helpers
// ---------------------------------------------------------------------------
__device__ __forceinline__ void mma16816(float* c, const uint32_t* a,
                                         const uint32_t* b) {
    asm volatile(
        "mma.sync.aligned.m16n8k16.row.col.f32.f16.f16.f32 "
        "{%0,%1,%2,%3}, {%4,%5,%6,%7}, {%8,%9}, {%0,%1,%2,%3};"
        : "+f"(c[0]), "+f"(c[1]), "+f"(c[2]), "+f"(c[3])
        : "r"(a[0]), "r"(a[1]), "r"(a[2]), "r"(a[3]), "r"(b[0]), "r"(b[1]));
}

// ---------------------------------------------------------------------------
// k_main: register-pipelined gather -> fp16-split 2-pass mma.sync GEMM
// Block: 512 threads (16 warps, 4m x 4n), tile 256o x 128p, K-chunk 16,
// double-buffered SMEM (plain LDG/STS; no cp.async, no ldmatrix).
// Grid: 8 n * 32 ptiles = 256 blocks.
// ---------------------------------------------------------------------------
__global__ __launch_bounds__(512, 1) void k_main(const float* __restrict__ x,
                                                 const float* __restrict__ b2,
                                                 float* __restrict__ out) {
    extern __shared__ __align__(16) char smem[];
    int tid = threadIdx.x;
    int wid = tid >> 5;
    int lane = tid & 31;
    int g  = lane >> 2;
    int t2 = lane & 3;

    int n     = blockIdx.x >> 5;
    int pbase = (blockIdx.x & 31) * 128;

    int o_base = (wid & 3) * 64;
    int p_base = (wid >> 2) * 32;
    int pg = tid & 127;          // gather position
    int jg = tid >> 7;           // gather ck-group (0..3), 4 ck each

    // ---- bilinear table: 9 taps x 128 positions ----
    for (int t = tid; t < 1152; t += 512) {
        int tap = t >> 7;
        int p   = t & 127;
        int hw  = pbase + p;
        int h   = hw >> 6;
        int w   = hw & 63;
        float dy = g_offset[(n * 18 + 2 * tap)     * HW + hw];
        float dx = g_offset[(n * 18 + 2 * tap + 1) * HW + hw];
        float py = (float)(h - 1 + tap / 3) + dy;
        float px = (float)(w - 1 + tap % 3) + dx;
        float fy = floorf(py), fx = floorf(px);
        float wy = py - fy, wx = px - fx;
        int y0 = (int)fy, x0 = (int)fx;
        float vy0 = ((unsigned)y0       < 64u) ? 1.f : 0.f;
        float vy1 = ((unsigned)(y0 + 1) < 64u) ? 1.f : 0.f;
        float vx0 = ((unsigned)x0       < 64u) ? 1.f : 0.f;
        float vx1 = ((unsigned)(x0 + 1) < 64u) ? 1.f : 0.f;
        float wy0 = (1.f - wy) * vy0, wy1 = wy * vy1;
        float wx0 = (1.f - wx) * vx0, wx1 = wx * vx1;
        int y0c = min(max(y0, 0), 63), y1c = min(max(y0 + 1, 0), 63);
        int x0c = min(max(x0, 0), 63), x1c = min(max(x0 + 1, 0), 63);
        int a00 = (y0c << 6) + x0c;
        int dxo = x1c - x0c;
        int dyo = (y1c - y0c) << 6;
        *(int2*)(smem + S_TABA + t * 8)    = make_int2(a00, dxo | (dyo << 16));
        *(float4*)(smem + S_TABW + t * 16) = make_float4(wy0 * wx0, wy0 * wx1,
                                                         wy1 * wx0, wy1 * wx1);
    }

    float acc[4][4][4];
#pragma unroll
    for (int mt = 0; mt < 4; mt++)
#pragma unroll
        for (int nt = 0; nt < 4; nt++)
#pragma unroll
            for (int j = 0; j < 4; j++) acc[mt][nt][j] = 0.f;

    const float* xn = x + ((size_t)n << 20);

    // W staging addressing: thread covers one 16B segment of hi and lo
    int wrow = tid >> 1;           // o
    int wseg = tid & 1;            // 0/1 (8 fp16 each)
    const uint4* wsrch = (const uint4*)(g_w2h) ;  // indexed per chunk below
    const uint4* wsrcl = (const uint4*)(g_w2l) ;

    __syncthreads();

    float raw[16];
    uint4 wregh, wregl;

    // ---- prologue: fetch + store chunk 0 into buf 0 ----
    {
        int ck0 = jg * 4;
        int c = ck0 / 9, tap = ck0 - c * 9;
#pragma unroll
        for (int kk = 0; kk < 4; kk++) {
            int t = (tap << 7) + pg;
            int2 ia = *(const int2*)(smem + S_TABA + t * 8);
            const float* xp = xn + (c << 12);
            int a00 = ia.x, dxo = ia.y & 0xFFFF, dyo = ia.y >> 16;
            raw[kk * 4 + 0] = __ldg(xp + a00);
            raw[kk * 4 + 1] = __ldg(xp + a00 + dxo);
            raw[kk * 4 + 2] = __ldg(xp + a00 + dyo);
            raw[kk * 4 + 3] = __ldg(xp + a00 + dyo + dxo);
            if (++tap == 9) { tap = 0; c++; }
        }
        int widx = (0 * COUT + wrow) * 2 + wseg;   // uint4 index into chunk 0
        wregh = wsrch[widx];
        wregl = wsrcl[widx];
    }

    for (int cb = 0; cb < NCH; cb++) {
        int cur = cb & 1;
        int nxt = cur ^ 1;

        // ---- store prefetched chunk cb into buf cur ----
        {
            // V: combine 4 taps -> fp16, pack pairs
            int ck0 = cb * KC + jg * 4;
            int tap = ck0 % 9;
            unsigned vb2[2];
#pragma unroll
            for (int kk = 0; kk < 4; kk++) {
                int t = (tap << 7) + pg;
                float4 wt = *(const float4*)(smem + S_TABW + t * 16);
                float v = wt.x * raw[kk * 4 + 0] + wt.y * raw[kk * 4 + 1]
                        + wt.z * raw[kk * 4 + 2] + wt.w * raw[kk * 4 + 3];
                unsigned short hv;
                asm("cvt.rn.f16.f32 %0, %1;" : "=h"(hv) : "f"(v));
                if (kk & 1) vb2[kk >> 1] |= ((unsigned)hv) << 16;
                else        vb2[kk >> 1]  = hv;
                if (++tap == 9) tap = 0;
            }
            *(uint2*)(smem + S_V0 + cur * 6144 + pg * WSTR + jg * 8)
                = make_uint2(vb2[0], vb2[1]);
            // W
            *(uint4*)(smem + S_WH0 + cur * 24576 + wrow * WSTR + wseg * 16) = wregh;
            *(uint4*)(smem + S_WH0 + cur * 24576 + 12288 + wrow * WSTR + wseg * 16) = wregl;
        }
        __syncthreads();

        // ---- issue prefetch for chunk cb+1 (LDGs fly under the MMAs) ----
        if (cb + 1 < NCH) {
            int ck0 = (cb + 1) * KC + jg * 4;
            int c = ck0 / 9, tap = ck0 - c * 9;
#pragma unroll
            for (int kk = 0; kk < 4; kk++) {
                int t = (tap << 7) + pg;
                int2 ia = *(const int2*)(smem + S_TABA + t * 8);
                const float* xp = xn + (c << 12);
                int a00 = ia.x, dxo = ia.y & 0xFFFF, dyo = ia.y >> 16;
                raw[kk * 4 + 0] = __ldg(xp + a00);
                raw[kk * 4 + 1] = __ldg(xp + a00 + dxo);
                raw[kk * 4 + 2] = __ldg(xp + a00 + dyo);
                raw[kk * 4 + 3] = __ldg(xp + a00 + dyo + dxo);
                if (++tap == 9) { tap = 0; c++; }
            }
            int widx = ((cb + 1) * COUT + wrow) * 2 + wseg;
            wregh = wsrch[widx];
            wregl = wsrcl[widx];
        }

        // ---- MMA on buf cur: 2 passes (wh*v, wl*v) ----
        const char* wh = smem + S_WH0 + cur * 24576;
        const char* wl = wh + 12288;
        const char* vv = smem + S_V0 + cur * 6144;

        uint32_t b[4][2];
#pragma unroll
        for (int nt = 0; nt < 4; nt++) {
            const char* rp = vv + (p_base + nt * 8 + g) * WSTR + t2 * 4;
            b[nt][0] = *(const uint32_t*)(rp);
            b[nt][1] = *(const uint32_t*)(rp + 16);
        }
#pragma unroll
        for (int mt = 0; mt < 4; mt++) {
            int ro = (o_base + mt * 16 + g) * WSTR + t2 * 4;
            uint32_t ah[4], al[4];
            ah[0] = *(const uint32_t*)(wh + ro);
            ah[1] = *(const uint32_t*)(wh + ro + 8 * WSTR);
            ah[2] = *(const uint32_t*)(wh + ro + 16);
            ah[3] = *(const uint32_t*)(wh + ro + 8 * WSTR + 16);
            al[0] = *(const uint32_t*)(wl + ro);
            al[1] = *(const uint32_t*)(wl + ro + 8 * WSTR);
            al[2] = *(const uint32_t*)(wl + ro + 16);
            al[3] = *(const uint32_t*)(wl + ro + 8 * WSTR + 16);
#pragma unroll
            for (int nt = 0; nt < 4; nt++) {
                mma16816(acc[mt][nt], ah, b[nt]);
                mma16816(acc[mt][nt], al, b[nt]);
            }
        }
        // note: no sync here — next iteration stores into buf nxt (disjoint),
        // and its pre-store sync orders those stores against these reads.
        __syncthreads();
    }

    // ---- epilogue: bias + float2 stores ----
#pragma unroll
    for (int mt = 0; mt < 4; mt++) {
        int o0 = o_base + mt * 16 + g;
        float bias0 = b2[o0];
        float bias1 = b2[o0 + 8];
        float* row0 = out + (size_t)(n * COUT + o0) * HW + pbase;
        float* row1 = row0 + 8 * HW;
#pragma unroll
        for (int nt = 0; nt < 4; nt++) {
            int p = p_base + nt * 8 + t2 * 2;
            *(float2*)(row0 + p) = make_float2(acc[mt][nt][0] + bias0,
                                               acc[mt][nt][1] + bias0);
            *(float2*)(row1 + p) = make_float2(acc[mt][nt][2] + bias1,
                                               acc[mt][nt][3] + bias1);
        }
    }
}

// ---------------------------------------------------------------------------
extern "C" void kernel_launch(void* const* d_in, const int* in_sizes, int n_in,
                              void* d_out, int out_size) {
    const float* x  = (const float*)d_in[0];
    const float* w1 = (const float*)d_in[1];
    const float* w2 = (const float*)d_in[2];
    const float* b2 = (const float*)d_in[3];
    float* out = (float*)d_out;

    cudaFuncSetAttribute(k_main, cudaFuncAttributeMaxDynamicSharedMemorySize,
                         S_TOTAL);

    k_prep<<<1152, 512>>>(w2);
    k_off<<<NB * 32, 256>>>(x, w1);
    k_main<<<NB * 32, 512, S_TOTAL>>>(x, b2, out);
}